// round 13
// baseline (speedup 1.0000x reference)
#include <cuda_runtime.h>
#include <cuda_bf16.h>
#include <cstdint>

// Problem constants
#define BATCH   32
#define NN      64
#define DD      512
#define MM      2080          // N*(N+1)/2
#define SORTN   4096
#define NTHR    512
#define TOPK    5
#define NEIGH   16
#define NEGK    16
#define TOTALS  85            // TOPK*(NEIGH+1)
#define KK      101           // NEGK + TOTALS
#define NSEG    65            // 2080/32 exact

// Output layout (concatenated float32): feat, pred_s_e, offset, score
#define FEAT_BASE 0
#define SE_BASE   (BATCH*KK*DD)
#define OFF_BASE  (SE_BASE + BATCH*KK*2)
#define SC_BASE   (OFF_BASE + BATCH*KK*2)

typedef unsigned long long u64;
typedef unsigned int u32;
typedef unsigned short u16;

__device__ u64 g_keys[BATCH * SORTN];               // 1MB sort scratch
__device__ int g_flag[BATCH];                       // producer->consumer flags (reset each run)

__device__ __forceinline__ u32 float_desc_key(float s) {
    u32 u = __float_as_uint(s);
    u32 k = (u & 0x80000000u) ? ~u : (u | 0x80000000u); // ascending map
    return ~k;                                          // descending
}

__device__ __forceinline__ u64 u64min(u64 a, u64 b) { return a < b ? a : b; }
__device__ __forceinline__ u64 u64max(u64 a, u64 b) { return a > b ? a : b; }

__device__ __forceinline__ void cswap(u64 &a, u64 &b, bool up) {
    if ((a > b) == up) { u64 t = a; a = b; b = t; }
}

__device__ __forceinline__ u32 warp_incl_scan(u32 v, int lane) {
    #pragma unroll
    for (int o = 1; o < 32; o <<= 1) {
        u32 t = __shfl_up_sync(0xFFFFFFFFu, v, o);
        if (lane >= o) v += t;
    }
    return v;
}

// lowest `rem` set bits of w
__device__ __forceinline__ u32 low_bits(u32 w, int rem) {
    if (rem <= 0) return 0;
    if (__popc(w) <= rem) return w;
    u32 x = w;
    #pragma unroll
    for (int q = 0; q < NEIGH; ++q)
        if (q < rem) x &= (x - 1);
    return w ^ x;
}

// 2-elem warp-local bitonic stages; eg = GLOBAL index of K[0], K[1] at eg+32.
__device__ __forceinline__ void reg_phase2(u64 K[2], int k, int jstart, int eg) {
    int j = jstart;
    if (j >= 32) {
        bool up = ((eg & k) == 0);
        cswap(K[0], K[1], up);
        j = 16;
    }
    for (; j >= 1; j >>= 1) {
        #pragma unroll
        for (int q = 0; q < 2; ++q) {
            int e = eg + q * 32;
            bool up = ((e & k) == 0);
            u64 o = __shfl_xor_sync(0xFFFFFFFFu, K[q], j);
            bool upper = (e & j) != 0;
            K[q] = (up != upper) ? u64min(K[q], o) : u64max(K[q], o);
        }
    }
}

// 8-elem warp-local bitonic stages; K[q] at ebase + q*32, ebase = warp*256+lane.
__device__ __forceinline__ void reg_phase8(u64 K[8], int k, int jstart, int ebase) {
    int j = jstart;
    if (j >= 128) {
        #pragma unroll
        for (int q = 0; q < 4; ++q) {
            bool up = (((ebase + q * 32) & k) == 0);
            cswap(K[q], K[q + 4], up);
        }
        j = 64;
    }
    if (j >= 64) {
        #pragma unroll
        for (int h = 0; h < 8; h += 4)
            #pragma unroll
            for (int q = 0; q < 2; ++q) {
                bool up = (((ebase + (h + q) * 32) & k) == 0);
                cswap(K[h + q], K[h + q + 2], up);
            }
        j = 32;
    }
    if (j >= 32) {
        #pragma unroll
        for (int q = 0; q < 8; q += 2) {
            bool up = (((ebase + q * 32) & k) == 0);
            cswap(K[q], K[q + 1], up);
        }
        j = 16;
    }
    for (; j >= 1; j >>= 1) {
        #pragma unroll
        for (int q = 0; q < 8; ++q) {
            int e = ebase + q * 32;
            bool up = ((e & k) == 0);
            u64 o = __shfl_xor_sync(0xFFFFFFFFu, K[q], j);
            bool upper = (e & j) != 0;
            K[q] = (up != upper) ? u64min(K[q], o) : u64max(K[q], o);
        }
    }
}

__global__ void __launch_bounds__(NTHR, 1)
fused_all(const float* __restrict__ score_pred,
          const float* __restrict__ map2d,
          const float* __restrict__ offset_gt,
          const float* __restrict__ tmap,
          float* __restrict__ out)
{
    __shared__ u64 skeys[SORTN];                    // 32KB (producers use first 2048)
    __shared__ u16 rc[MM];
    __shared__ u16 smom[MM];
    __shared__ u32 maskw[NSEG], supw[NSEG], selw[NSEG];
    __shared__ u16 unsup_idx[MM];
    __shared__ u16 sel_idx[TOTALS];
    __shared__ u32 upref[NSEG + 1], spref[NSEG + 1];
    __shared__ u32 s_sel[KK];

    const int tid  = threadIdx.x;
    const int lane = tid & 31;
    const int warp = tid >> 5;

    if (blockIdx.x < 2 * BATCH) {
        // ================= PRODUCER: sort one 2048-half of batch h/2 =================
        const int h  = blockIdx.x;
        const int b  = h >> 1;
        const bool hp_up = ((h & 1) == 0);          // k=2048 direction (global bit 11)
        const int elo = (h & 1) * 2048;             // element range [elo, elo+2048)
        const int ebase2 = warp * 64 + lane;        // quarter layout: 2 elems/thread

        skeys[tid] = ~0ULL; skeys[tid + 512] = ~0ULL;
        skeys[tid + 1024] = ~0ULL; skeys[tid + 1536] = ~0ULL;
        __syncthreads();
        #pragma unroll
        for (int idx = tid; idx < NN * NN; idx += NTHR) {
            int r = idx >> 6, c = idx & 63;
            if (c >= r) {
                int e = (r * (129 - r)) / 2 + (c - r);
                int le = e - elo;
                if (le >= 0 && le < 2048) {
                    float s = score_pred[b * (NN * NN) + idx];
                    skeys[le] = ((u64)float_desc_key(s) << 32) | (u32)e;
                }
            }
        }
        __syncthreads();

        // ---- two quarter sorts (k = 2..1024) ----
        for (int qi = 0; qi < 2; ++qi) {
            u64* sq = skeys + qi * 1024;
            const int eg = h * 2048 + qi * 1024 + ebase2;
            u64 K[2];
            K[0] = sq[ebase2]; K[1] = sq[ebase2 + 32];

            for (int k = 2; k <= 64; k <<= 1)
                reg_phase2(K, k, (k >> 1) > 32 ? 32 : (k >> 1), eg);

            // k=128: smem j=64
            sq[ebase2] = K[0]; sq[ebase2 + 32] = K[1];
            __syncthreads();
            {
                int i = ((tid & ~63) << 1) | (tid & 63);
                int p = i | 64;
                bool up = ((i & 128) == 0);
                u64 a = sq[i], c2 = sq[p];
                if ((a > c2) == up) { sq[i] = c2; sq[p] = a; }
            }
            __syncthreads();
            K[0] = sq[ebase2]; K[1] = sq[ebase2 + 32];
            reg_phase2(K, 128, 32, eg);

            // k=256: fused2 (128,64)
            sq[ebase2] = K[0]; sq[ebase2 + 32] = K[1];
            __syncthreads();
            if (tid < 256) {
                int base = ((tid & ~63) << 2) | (tid & 63);
                bool up = ((base & 256) == 0);
                u64 a0 = sq[base], a1 = sq[base + 64], a2 = sq[base + 128], a3 = sq[base + 192];
                cswap(a0, a2, up); cswap(a1, a3, up);
                cswap(a0, a1, up); cswap(a2, a3, up);
                sq[base] = a0; sq[base + 64] = a1; sq[base + 128] = a2; sq[base + 192] = a3;
            }
            __syncthreads();
            K[0] = sq[ebase2]; K[1] = sq[ebase2 + 32];
            reg_phase2(K, 256, 32, eg);

            // k=512: fused3 (256,128,64)
            sq[ebase2] = K[0]; sq[ebase2 + 32] = K[1];
            __syncthreads();
            if (tid < 128) {
                int base = ((tid & ~63) << 3) | (tid & 63);
                bool up = ((base & 512) == 0);
                u64 a[8];
                #pragma unroll
                for (int m = 0; m < 8; ++m) a[m] = sq[base + m * 64];
                #pragma unroll
                for (int m = 0; m < 4; ++m) cswap(a[m], a[m + 4], up);
                cswap(a[0], a[2], up); cswap(a[1], a[3], up);
                cswap(a[4], a[6], up); cswap(a[5], a[7], up);
                #pragma unroll
                for (int m = 0; m < 8; m += 2) cswap(a[m], a[m + 1], up);
                #pragma unroll
                for (int m = 0; m < 8; ++m) sq[base + m * 64] = a[m];
            }
            __syncthreads();
            K[0] = sq[ebase2]; K[1] = sq[ebase2 + 32];
            reg_phase2(K, 512, 32, eg);

            // k=1024: fused2 (512,256) + fused2 (128,64) + tail; direction = quarter parity
            const bool qup = (qi == 0);
            sq[ebase2] = K[0]; sq[ebase2 + 32] = K[1];
            __syncthreads();
            if (tid < 256) {
                int base = tid;
                u64 a0 = sq[base], a1 = sq[base + 256], a2 = sq[base + 512], a3 = sq[base + 768];
                cswap(a0, a2, qup); cswap(a1, a3, qup);
                cswap(a0, a1, qup); cswap(a2, a3, qup);
                sq[base] = a0; sq[base + 256] = a1; sq[base + 512] = a2; sq[base + 768] = a3;
            }
            __syncthreads();
            if (tid < 256) {
                int base = ((tid & ~63) << 2) | (tid & 63);
                u64 a0 = sq[base], a1 = sq[base + 64], a2 = sq[base + 128], a3 = sq[base + 192];
                cswap(a0, a2, qup); cswap(a1, a3, qup);
                cswap(a0, a1, qup); cswap(a2, a3, qup);
                sq[base] = a0; sq[base + 64] = a1; sq[base + 128] = a2; sq[base + 192] = a3;
            }
            __syncthreads();
            K[0] = sq[ebase2]; K[1] = sq[ebase2 + 32];
            reg_phase2(K, 1024, 32, eg);
            sq[ebase2] = K[0]; sq[ebase2 + 32] = K[1];
            __syncthreads();
        }

        // ---- k=2048 phase over skeys[0..2048), direction hp_up everywhere ----
        if (tid < 256) {                            // fused3 (1024,512,256)
            u64 a[8];
            #pragma unroll
            for (int m = 0; m < 8; ++m) a[m] = skeys[tid + m * 256];
            #pragma unroll
            for (int m = 0; m < 4; ++m) cswap(a[m], a[m + 4], hp_up);
            cswap(a[0], a[2], hp_up); cswap(a[1], a[3], hp_up);
            cswap(a[4], a[6], hp_up); cswap(a[5], a[7], hp_up);
            #pragma unroll
            for (int m = 0; m < 8; m += 2) cswap(a[m], a[m + 1], hp_up);
            #pragma unroll
            for (int m = 0; m < 8; ++m) skeys[tid + m * 256] = a[m];
        }
        __syncthreads();
        #pragma unroll
        for (int it = 0; it < 2; ++it) {            // j=128
            int t = tid + it * NTHR;                // t < 1024
            int i = ((t & ~127) << 1) | (t & 127);
            int p = i | 128;
            u64 a = skeys[i], c2 = skeys[p];
            if ((a > c2) == hp_up) { skeys[i] = c2; skeys[p] = a; }
        }
        __syncthreads();
        {                                           // 4-reg warp tail j=64..1
            int ebase4 = warp * 128 + lane;
            u64 A0 = skeys[ebase4], A1 = skeys[ebase4 + 32];
            u64 A2 = skeys[ebase4 + 64], A3 = skeys[ebase4 + 96];
            cswap(A0, A2, hp_up); cswap(A1, A3, hp_up);     // j=64
            cswap(A0, A1, hp_up); cswap(A2, A3, hp_up);     // j=32
            u64 A[4] = {A0, A1, A2, A3};
            for (int j = 16; j >= 1; j >>= 1) {
                #pragma unroll
                for (int q = 0; q < 4; ++q) {
                    u64 o = __shfl_xor_sync(0xFFFFFFFFu, A[q], j);
                    bool upper = (lane & j) != 0;
                    A[q] = (hp_up != upper) ? u64min(A[q], o) : u64max(A[q], o);
                }
            }
            size_t gb = (size_t)b * SORTN + (size_t)(h & 1) * 2048;
            g_keys[gb + ebase4]      = A[0];
            g_keys[gb + ebase4 + 32] = A[1];
            g_keys[gb + ebase4 + 64] = A[2];
            g_keys[gb + ebase4 + 96] = A[3];
        }
        __syncthreads();
        if (tid == 0) { __threadfence(); atomicAdd(&g_flag[b], 1); }
        return;
    }

    // ================= CONSUMER: merge k=4096 + NMS + outputs + gather =================
    const int b = blockIdx.x - 2 * BATCH;
    const int ebase = warp * 256 + lane;

    // rc table (no dependency on producers)
    #pragma unroll
    for (int idx = tid; idx < NN * NN; idx += NTHR) {
        int r = idx >> 6, c = idx & 63;
        if (c >= r) {
            int e = (r * (129 - r)) / 2 + (c - r);
            rc[e] = (u16)(r | (c << 8));
        }
    }
    if (tid < NSEG) { supw[tid] = 0u; selw[tid] = 0u; }

    // wait for both halves of this batch
    if (tid == 0) {
        while (atomicAdd(&g_flag[b], 0) < 2) __nanosleep(64);
        __threadfence();
    }
    __syncthreads();

    #pragma unroll
    for (int i = tid; i < SORTN; i += NTHR)
        skeys[i] = g_keys[(size_t)b * SORTN + i];
    __syncthreads();
    if (tid == 0) atomicExch(&g_flag[b], 0);        // reset for next replay

    // ---- k=4096: fused4 (2048,1024,512,256) + warp tail ----
    u64 K[8];
    if (tid < 256) {
        int base = tid;
        u64 a[16];
        #pragma unroll
        for (int m = 0; m < 16; ++m) a[m] = skeys[base + m * 256];
        #pragma unroll
        for (int m = 0; m < 8; ++m) cswap(a[m], a[m + 8], true);    // j=2048
        #pragma unroll
        for (int h2 = 0; h2 < 16; h2 += 8)
            #pragma unroll
            for (int m = 0; m < 4; ++m) cswap(a[h2 + m], a[h2 + m + 4], true); // j=1024
        #pragma unroll
        for (int h2 = 0; h2 < 16; h2 += 4) {
            cswap(a[h2], a[h2 + 2], true); cswap(a[h2 + 1], a[h2 + 3], true);  // j=512
        }
        #pragma unroll
        for (int m = 0; m < 16; m += 2) cswap(a[m], a[m + 1], true);           // j=256
        #pragma unroll
        for (int m = 0; m < 16; ++m) skeys[base + m * 256] = a[m];
    }
    __syncthreads();
    #pragma unroll
    for (int q = 0; q < 8; ++q) K[q] = skeys[ebase + q * 32];
    reg_phase8(K, 4096, 128, ebase);
    #pragma unroll
    for (int q = 0; q < 8; ++q) skeys[ebase + q * 32] = K[q];
    __syncthreads();

    // ---- sorted moments (regs + smem) ----
    u32 mreg[5];
    #pragma unroll
    for (int rd = 0; rd < 5; ++rd) {
        int i = tid + rd * NTHR;
        u32 v = 0;
        if (i < MM) {
            u32 e = (u32)skeys[i];
            u32 rcv = rc[e];
            int s = rcv & 0xFF;
            int en = (rcv >> 8) + 1;
            v = (u32)(s | (en << 8));
            smom[i] = (u16)v;
        }
        mreg[rd] = v;
    }
    __syncthreads();

    // ---- greedy NMS (2 barriers/iter) ----
    {
        int i = 0, cnt = 0;
        while (cnt < TOPK) {
            {
                int s2 = i >> 5;
                u32 w = (~supw[s2]) & (0xFFFFFFFFu << (i & 31));
                while (w == 0 && s2 < NSEG - 1) { ++s2; w = ~supw[s2]; }
                i = w ? (s2 * 32 + __ffs(w) - 1) : MM;
            }
            if (i >= MM - 1) break;

            const int iseg = i >> 5;
            const u32 ibit = 1u << (i & 31);
            u32 mi = smom[i];
            int si = mi & 0xFF, ei = mi >> 8;

            #pragma unroll
            for (int rd = 0; rd < 5; ++rd) {
                int e2 = tid + rd * NTHR;
                bool mk = false;
                if (e2 < MM) {
                    if (e2 == i) mk = true;
                    else if (e2 > i) {
                        u32 mmv = mreg[rd];
                        int s3 = mmv & 0xFF, e3 = mmv >> 8;
                        int inter = min(e3, ei) - max(s3, si);
                        if (inter > 0) {
                            int uni = max(e3, ei) - min(s3, si);
                            mk = (2 * inter > uni);
                        }
                    }
                }
                u32 bal = __ballot_sync(0xFFFFFFFFu, mk);
                int seg = warp + rd * 16;
                if (lane == 0 && seg < NSEG) maskw[seg] = bal;
            }
            __syncthreads();

            if (warp == 0) {
                u32 full0 = maskw[lane];
                u32 full1 = maskw[lane + 32];
                u32 full2 = (lane == 0) ? maskw[64] : 0;
                u32 m0 = full0, m1 = full1, m2 = full2;
                if (lane == iseg)        m0 &= ~ibit;
                if (lane + 32 == iseg)   m1 &= ~ibit;
                if (lane == 0 && iseg == 64) m2 &= ~ibit;
                u32 v0 = __popc(m0), v1 = __popc(m1);
                u32 s0 = warp_incl_scan(v0, lane);
                u32 t0 = __shfl_sync(0xFFFFFFFFu, s0, 31);
                u32 s1 = warp_incl_scan(v1, lane) + t0;
                u32 nb0 = s0 - v0;
                u32 nb1 = s1 - v1;
                u32 nb2 = __shfl_sync(0xFFFFFFFFu, s1, 31);
                supw[lane]      |= full0;
                supw[lane + 32] |= full1;
                if (lane == 0) supw[64] |= full2;
                u32 add0 = low_bits(m0, NEIGH - (int)nb0);
                if (lane == iseg) add0 |= ibit;
                if (add0) selw[lane] |= add0;
                u32 add1 = low_bits(m1, NEIGH - (int)nb1);
                if (lane + 32 == iseg) add1 |= ibit;
                if (add1) selw[lane + 32] |= add1;
                if (lane == 0) {
                    u32 add2 = low_bits(m2, NEIGH - (int)nb2);
                    if (iseg == 64) add2 |= ibit;
                    if (add2) selw[64] |= add2;
                }
            }
            __syncthreads();
            ++i; ++cnt;
        }
        __syncthreads();
    }

    // ---- parallel compactions ----
    if (warp == 0) {
        u32 v0 = __popc(~supw[lane]);
        u32 v1 = __popc(~supw[lane + 32]);
        u32 v2 = (lane == 0) ? __popc(~supw[64]) : 0;
        u32 s0 = warp_incl_scan(v0, lane);
        u32 t0 = __shfl_sync(0xFFFFFFFFu, s0, 31);
        u32 s1 = warp_incl_scan(v1, lane) + t0;
        u32 t1 = __shfl_sync(0xFFFFFFFFu, s1, 31);
        upref[lane]      = s0 - v0;
        upref[lane + 32] = s1 - v1;
        if (lane == 0) { upref[64] = t1; upref[65] = t1 + v2; }
    }
    if (warp == 1) {
        u32 v0 = __popc(selw[lane]);
        u32 v1 = __popc(selw[lane + 32]);
        u32 v2 = (lane == 0) ? __popc(selw[64]) : 0;
        u32 s0 = warp_incl_scan(v0, lane);
        u32 t0 = __shfl_sync(0xFFFFFFFFu, s0, 31);
        u32 s1 = warp_incl_scan(v1, lane) + t0;
        u32 t1 = __shfl_sync(0xFFFFFFFFu, s1, 31);
        spref[lane]      = s0 - v0;
        spref[lane + 32] = s1 - v1;
        if (lane == 0) { spref[64] = t1; spref[65] = t1 + v2; }
    }
    #pragma unroll
    for (int t = tid; t < MM; t += NTHR) unsup_idx[t] = (u16)(MM - 1);
    if (tid >= NTHR - TOTALS) sel_idx[tid - (NTHR - TOTALS)] = (u16)(MM - 1);
    __syncthreads();

    #pragma unroll
    for (int e2 = tid; e2 < MM; e2 += NTHR) {
        int s2 = e2 >> 5;
        u32 bit = 1u << (e2 & 31);
        u32 low = bit - 1u;
        u32 uw = ~supw[s2];
        if (uw & bit) unsup_idx[upref[s2] + __popc(uw & low)] = (u16)e2;
        u32 sw = selw[s2];
        if (sw & bit) sel_idx[spref[s2] + __popc(sw & low)] = (u16)e2;
    }
    __syncthreads();

    // ---- final index assembly + small outputs ----
    if (tid < KK) {
        int n_unsup = (int)upref[NSEG];
        int n_sel   = (int)spref[NSEG];
        int pad     = TOTALS - n_sel;

        int idxS;
        if (tid < NEGK) {
            int t = n_unsup - 1 - tid;
            if (t < 0) t = 0;
            if (t > MM - 1) t = MM - 1;
            idxS = unsup_idx[t];
        } else {
            int p = tid - NEGK;
            if (p < pad) idxS = unsup_idx[p];
            else {
                int q = p - pad;
                if (q > TOTALS - 1) q = TOTALS - 1;
                idxS = sel_idx[q];
            }
        }
        u32 orig = (u32)skeys[idxS];
        u32 rcv  = rc[orig];
        int r = rcv & 0xFF;
        int c = rcv >> 8;

        int gk = b * KK + tid;
        s_sel[tid] = (u32)(r * NN + c);

        out[SE_BASE + gk * 2 + 0] = (float)r;
        out[SE_BASE + gk * 2 + 1] = (float)(c + 1);

        size_t oidx = ((size_t)(b * NN + r) * NN + c) * 2;
        out[OFF_BASE + gk * 2 + 0] = offset_gt[oidx + 0];
        out[OFF_BASE + gk * 2 + 1] = offset_gt[oidx + 1];

        out[SC_BASE + gk] = tmap[(size_t)(b * NN + r) * NN + c];
    }
    __syncthreads();

    // ---- feature gather: batched loads for MLP (3 rounds of <=9 outstanding) ----
    {
        const float4* __restrict__ src4 = (const float4*)map2d;
        float4* __restrict__ dst4 = (float4*)(out + FEAT_BASE);
        const size_t bbase = (size_t)b * (NN * NN) * (DD / 4);
        const size_t obase = (size_t)b * KK * (DD / 4);
        const int total = KK * (DD / 4);            // 12928
        #pragma unroll 1
        for (int s0 = 0; s0 < 26; s0 += 9) {
            float4 v[9];
            #pragma unroll
            for (int m = 0; m < 9; ++m) {
                int s = s0 + m;
                int t = tid + s * NTHR;
                if (s < 26 && t < total) {
                    int row = t >> 7, q = t & 127;
                    v[m] = src4[bbase + (size_t)s_sel[row] * (DD / 4) + q];
                }
            }
            #pragma unroll
            for (int m = 0; m < 9; ++m) {
                int s = s0 + m;
                int t = tid + s * NTHR;
                if (s < 26 && t < total) {
                    int row = t >> 7, q = t & 127;
                    dst4[obase + (size_t)row * (DD / 4) + q] = v[m];
                }
            }
        }
    }
}

extern "C" void kernel_launch(void* const* d_in, const int* in_sizes, int n_in,
                              void* d_out, int out_size)
{
    const float* score_pred = (const float*)d_in[0];
    // d_in[1] = map2d_mask (deterministic triu — not needed)
    const float* map2d      = (const float*)d_in[2];
    const float* offset_gt  = (const float*)d_in[3];
    const float* tmap       = (const float*)d_in[4];
    float* out = (float*)d_out;

    fused_all<<<3 * BATCH, NTHR>>>(score_pred, map2d, offset_gt, tmap, out);
}